// round 8
// baseline (speedup 1.0000x reference)
#include <cuda_runtime.h>

#define TT    2048
#define BB    32
#define FEATD 512
#define HIDD  512
#define NCOL4 2048
#define NCTA  128
#define NH    4
#define NC    16
#define NTHR  256
#define ROWSZ (BB*HIDD)      // 16384 floats per timestep of h

// smem layout (floats)
#define ZX_OFF   0            // z_x: [32][512]
#define ZH_OFF   16384        // z_h: [32][512]
#define W_OFF    32768        // W_s: 16384
#define G_OFF    49152        // gates: 32*17
#define SMEM_FLOATS (G_OFF + 32*17)   // ~194 KB

__device__ __align__(256) float g_hA[(TT+1)*ROWSZ];
__device__ __align__(256) float g_hB[(TT+1)*ROWSZ];
__device__ volatile unsigned int g_arr[NCTA];   // per-CTA arrival counters (monotonic)

// JAX silently downcasts int64->int32 unless x64 mode is on; detect at runtime.
__device__ __forceinline__ int load_length(const void* lp, int b) {
    const int* L = (const int*)lp;
    bool is64 = true;
    #pragma unroll
    for (int w = 1; w < 32; w += 2) is64 &= (L[w] == 0);
    return is64 ? (int)((const long long*)lp)[b] : L[b];
}

__device__ __forceinline__ void cpa16(unsigned int dst, const void* src) {
    asm volatile("cp.async.cg.shared.global [%0], [%1], 16;" :: "r"(dst), "l"(src));
}
#define CPA_COMMIT() asm volatile("cp.async.commit_group;")
#define CPA_WAIT0()  asm volatile("cp.async.wait_group 0;")

__device__ __forceinline__ unsigned int smem_u32(const void* p) {
    unsigned int a;
    asm("{ .reg .u64 t; cvta.to.shared.u64 t, %1; cvt.u32.u64 %0, t; }" : "=r"(a) : "l"(p));
    return a;
}

// Distributed grid barrier: each CTA stores its own slot (no contention),
// 128 threads poll the 128 packed counters (4 cache lines). 'target' is
// monotonic across graph replays (base read at kernel start).
__device__ __forceinline__ void grid_barrier(unsigned int target) {
    __syncthreads();          // CTA done with this step's smem + h STG issued
    __threadfence();          // h STGs globally visible before flag
    if (threadIdx.x == 0) g_arr[blockIdx.x] = target;
    if (threadIdx.x < NCTA) {
        while ((int)(g_arr[threadIdx.x] - target) < 0) {}
    }
    __syncthreads();
}

__global__ void __launch_bounds__(NTHR, 1)
lstm_persistent(const float* __restrict__ x,
                const void* __restrict__ length,
                const float* __restrict__ Wih0, const float* __restrict__ Whh0,
                const float* __restrict__ b0v,
                const float* __restrict__ Wih1, const float* __restrict__ Whh1,
                const float* __restrict__ b1v)
{
    extern __shared__ float smem[];
    float* z_x     = smem + ZX_OFF;
    float* z_h     = smem + ZH_OFF;
    float* W_s     = smem + W_OFF;
    float* gates_s = smem + G_OFF;
    const unsigned int zx_u = smem_u32(z_x);
    const unsigned int zh_u = smem_u32(z_h);

    const int tid   = threadIdx.x;
    const int hbase = blockIdx.x * NH;

    // barrier base: all slots equal at every launch start (monotonic forever)
    const unsigned int bar_base = g_arr[blockIdx.x];

    const int c   = tid & 15;              // gate column (c = hh*4 + gate)
    const int bh  = (tid >> 4) & 1;
    const int bg  = (tid >> 5) & 3;
    const int kh  = tid >> 7;              // k-half within each 512-K block
    const int b0i = bg*8 + bh*4;           // 4 batch rows per thread

    const int eb  = tid & 31;              // elementwise mapping (tid<128)
    const int ehh = tid >> 5;
    int lb = 0;
    if (tid < 128) lb = load_length(length, eb);

    for (int layer = 0; layer < 2; ++layer) {
        const float* Wih  = layer ? Wih1 : Wih0;
        const float* Whh  = layer ? Whh1 : Whh0;
        const float* bias = layer ? b1v  : b0v;
        const float* xbase = layer ? (g_hA + ROWSZ) : x;
        float* hbuf = layer ? g_hB : g_hA;

        // Stage weights: W_s[(k>>2)*64 + c*4 + (k&3)] = W[k][col(c)]
        __syncthreads();
        for (int i = tid; i < 1024*NC; i += NTHR) {
            int k  = i >> 4;
            int cc = i & 15;
            int col = ((cc & 3) << 9) + hbase + (cc >> 2);
            float w = (k < FEATD) ? Wih[(size_t)k*NCOL4 + col]
                                  : Whh[(size_t)(k-FEATD)*NCOL4 + col];
            W_s[((k >> 2) << 6) + (cc << 2) + (k & 3)] = w;
        }
        float bv = bias[((c & 3) << 9) + hbase + (c >> 2)];

        // load x(0) into z_x
        {
            const float* xrow = xbase;
            #pragma unroll
            for (int j = 0; j < 16; ++j) {
                int i = tid + j*NTHR;
                int b = i >> 7, k4 = i & 127;
                cpa16(zx_u + ((b << 9) + (k4 << 2))*4, xrow + b*512 + (k4 << 2));
            }
            CPA_COMMIT();
        }
        CPA_WAIT0();
        __syncthreads();

        float creg = 0.f, hreg = 0.f;

        for (int t = 0; t < TT; ++t) {
            // 1) stage h(t) asynchronously; awaited after the x-GEMM
            {
                const float* hrow = hbuf + (size_t)t*ROWSZ;
                #pragma unroll
                for (int j = 0; j < 16; ++j) {
                    int i = tid + j*NTHR;
                    int b = i >> 7, k4 = i & 127;
                    cpa16(zh_u + ((b << 9) + (k4 << 2))*4, hrow + b*512 + (k4 << 2));
                }
                CPA_COMMIT();
            }

            // 2) prefetch x(t+1) into registers (latency hidden by x-GEMM)
            float4 xp[16];
            {
                int tn = (t + 1 < TT) ? (t + 1) : (TT - 1);
                const float4* xnext = (const float4*)(xbase + (size_t)tn*ROWSZ);
                #pragma unroll
                for (int j = 0; j < 16; ++j)
                    xp[j] = __ldcg(xnext + tid + j*NTHR);
            }

            float a0 = 0.f, a1 = 0.f, a2 = 0.f, a3 = 0.f;

            // 3) x-GEMM: k in [0,512), this thread kh*256..+256
            {
                const float* wp = W_s + ((kh*256) >> 2)*64 + (c << 2);
                const float* zp = z_x + b0i*512 + kh*256;
                #pragma unroll 8
                for (int k4 = 0; k4 < 64; ++k4) {
                    float4 w  = *(const float4*)(wp + (k4 << 6));
                    float4 z0 = *(const float4*)(zp + (k4 << 2));
                    float4 z1 = *(const float4*)(zp + 512  + (k4 << 2));
                    float4 z2 = *(const float4*)(zp + 1024 + (k4 << 2));
                    float4 z3 = *(const float4*)(zp + 1536 + (k4 << 2));
                    a0 += z0.x*w.x; a0 += z0.y*w.y; a0 += z0.z*w.z; a0 += z0.w*w.w;
                    a1 += z1.x*w.x; a1 += z1.y*w.y; a1 += z1.z*w.z; a1 += z1.w*w.w;
                    a2 += z2.x*w.x; a2 += z2.y*w.y; a2 += z2.z*w.z; a2 += z2.w*w.w;
                    a3 += z3.x*w.x; a3 += z3.y*w.y; a3 += z3.z*w.z; a3 += z3.w*w.w;
                }
            }

            // 4) h(t) must be resident; also closes all z_x reads of step t
            CPA_WAIT0();
            __syncthreads();

            // 5) store x(t+1) to z_x (all step-t reads completed at the sync)
            #pragma unroll
            for (int j = 0; j < 16; ++j) {
                int i = tid + j*NTHR;
                int b = i >> 7, k4 = i & 127;
                *(float4*)(z_x + (b << 9) + (k4 << 2)) = xp[j];
            }

            // 6) h-GEMM: k in [512,1024)
            {
                const float* wp = W_s + ((512 + kh*256) >> 2)*64 + (c << 2);
                const float* zp = z_h + b0i*512 + kh*256;
                #pragma unroll 8
                for (int k4 = 0; k4 < 64; ++k4) {
                    float4 w  = *(const float4*)(wp + (k4 << 6));
                    float4 z0 = *(const float4*)(zp + (k4 << 2));
                    float4 z1 = *(const float4*)(zp + 512  + (k4 << 2));
                    float4 z2 = *(const float4*)(zp + 1024 + (k4 << 2));
                    float4 z3 = *(const float4*)(zp + 1536 + (k4 << 2));
                    a0 += z0.x*w.x; a0 += z0.y*w.y; a0 += z0.z*w.z; a0 += z0.w*w.w;
                    a1 += z1.x*w.x; a1 += z1.y*w.y; a1 += z1.z*w.z; a1 += z1.w*w.w;
                    a2 += z2.x*w.x; a2 += z2.y*w.y; a2 += z2.z*w.z; a2 += z2.w*w.w;
                    a3 += z3.x*w.x; a3 += z3.y*w.y; a3 += z3.z*w.z; a3 += z3.w*w.w;
                }
            }

            // 7) cross-kh reduce via smem
            if (kh == 1) {
                gates_s[(b0i+0)*17 + c] = a0;
                gates_s[(b0i+1)*17 + c] = a1;
                gates_s[(b0i+2)*17 + c] = a2;
                gates_s[(b0i+3)*17 + c] = a3;
            }
            __syncthreads();
            if (kh == 0) {
                gates_s[(b0i+0)*17 + c] += a0 + bv;
                gates_s[(b0i+1)*17 + c] += a1 + bv;
                gates_s[(b0i+2)*17 + c] += a2 + bv;
                gates_s[(b0i+3)*17 + c] += a3 + bv;
            }
            __syncthreads();

            // 8) LSTM elementwise: thread owns (b, hidden) state
            if (tid < 128) {
                float fg = gates_s[eb*17 + ehh*4 + 0];
                float ig = gates_s[eb*17 + ehh*4 + 1];
                float og = gates_s[eb*17 + ehh*4 + 2];
                float gg = gates_s[eb*17 + ehh*4 + 3];
                float cn, hn;
                if (t < lb) {
                    float sf = __fdividef(1.f, 1.f + __expf(-fg));
                    float si = __fdividef(1.f, 1.f + __expf(-ig));
                    float so = __fdividef(1.f, 1.f + __expf(-og));
                    float tg = 2.f*__fdividef(1.f, 1.f + __expf(-2.f*gg)) - 1.f;
                    cn = sf*creg + si*tg;
                    float tc = 2.f*__fdividef(1.f, 1.f + __expf(-2.f*cn)) - 1.f;
                    hn = so*tc;
                } else {
                    cn = creg;
                    hn = hreg;
                }
                creg = cn;
                hreg = hn;
                hbuf[(size_t)(t+1)*ROWSZ + eb*HIDD + hbase + ehh] = hn;
            }
            grid_barrier(bar_base + (unsigned)(layer*TT + t + 1));
        }
    }
}

// out[r][a] = h1[r] . Wfc[:,a] + bfc[a],  h1 row = g_hB row r+32
__global__ void __launch_bounds__(256)
fc_kernel(const float* __restrict__ Wfc, const float* __restrict__ bfc,
          float* __restrict__ out)
{
    __shared__ float w_s[128*64];
    __shared__ float h_s[32*128];
    const int tid = threadIdx.x;
    const int rbase = blockIdx.x * 32;
    const int a  = tid & 63;
    const int r4 = tid >> 6;

    float acc[8];
    float bvv = bfc[a];
    #pragma unroll
    for (int j = 0; j < 8; ++j) acc[j] = bvv;

    for (int kc = 0; kc < 512; kc += 128) {
        __syncthreads();
        for (int i = tid; i < 128*64/4; i += 256)
            ((float4*)w_s)[i] = ((const float4*)(Wfc + (size_t)kc*64))[i];
        for (int i = tid; i < 32*128/4; i += 256) {
            int r  = i >> 5;
            int k4 = i & 31;
            ((float4*)(h_s + r*128))[k4] =
                *(const float4*)(g_hB + (size_t)(rbase + r + BB)*HIDD + kc + (k4 << 2));
        }
        __syncthreads();
        #pragma unroll 4
        for (int k = 0; k < 128; ++k) {
            float w = w_s[(k << 6) + a];
            #pragma unroll
            for (int j = 0; j < 8; ++j)
                acc[j] += h_s[(r4 + 4*j)*128 + k] * w;
        }
    }
    #pragma unroll
    for (int j = 0; j < 8; ++j)
        out[(size_t)(rbase + r4 + 4*j)*64 + a] = acc[j];
}

extern "C" void kernel_launch(void* const* d_in, const int* in_sizes, int n_in,
                              void* d_out, int out_size)
{
    const float* x      = (const float*)d_in[0];
    const void*  length = (const void*)d_in[1];
    const float* Wih0   = (const float*)d_in[2];
    const float* Whh0   = (const float*)d_in[3];
    const float* b0v    = (const float*)d_in[4];
    const float* Wih1   = (const float*)d_in[5];
    const float* Whh1   = (const float*)d_in[6];
    const float* b1v    = (const float*)d_in[7];
    const float* Wfc    = (const float*)d_in[8];
    const float* bfc    = (const float*)d_in[9];
    float* out = (float*)d_out;

    const int smem_bytes = SMEM_FLOATS * (int)sizeof(float); // ~194 KB
    cudaFuncSetAttribute(lstm_persistent,
                         cudaFuncAttributeMaxDynamicSharedMemorySize, smem_bytes);

    lstm_persistent<<<NCTA, NTHR, smem_bytes>>>(x, length, Wih0, Whh0, b0v,
                                                Wih1, Whh1, b1v);
    fc_kernel<<<(TT*BB)/32, 256>>>(Wfc, bfc, out);
}

// round 9
// speedup vs baseline: 1.4804x; 1.4804x over previous
#include <cuda_runtime.h>

#define TT    2048
#define BB    32
#define FEATD 512
#define HIDD  512
#define NCOL4 2048
#define NCTA  128
#define NH    4
#define NC    16
#define NTHR  256
#define ROWSZ (BB*HIDD)      // 16384 floats per timestep of h
#define ZS    516            // padded z row stride (floats): 4*ZS % 32 == 16 -> no bank conflict

// smem layout (floats)
#define ZX_OFF   0                    // z_x: [32][516]
#define ZH_OFF   (32*ZS)              // z_h: [32][516]
#define W_OFF    (2*32*ZS)            // W_s: 16384
#define G_OFF    (W_OFF + 16384)      // gates: 32*17
#define SMEM_FLOATS (G_OFF + 32*17)   // ~199.8 KB

__device__ __align__(256) float g_hA[(TT+1)*ROWSZ];
__device__ __align__(256) float g_hB[(TT+1)*ROWSZ];
__device__ unsigned int g_count = 0;
__device__ unsigned int g_gen   = 0;

// Single-counter atomic grid barrier (R6-proven). g_gen monotonic across
// graph replays; g_count returns to 0 at every barrier.
__device__ __forceinline__ void grid_barrier() {
    __threadfence();
    __syncthreads();
    if (threadIdx.x == 0) {
        volatile unsigned int* vgen = &g_gen;
        unsigned int gen = *vgen;
        if (atomicAdd(&g_count, 1u) == NCTA - 1u) {
            atomicExch(&g_count, 0u);
            __threadfence();
            atomicAdd(&g_gen, 1u);
        } else {
            while (*vgen == gen) {}
        }
    }
    __syncthreads();
}

// JAX silently downcasts int64->int32 unless x64 mode is on; detect at runtime.
__device__ __forceinline__ int load_length(const void* lp, int b) {
    const int* L = (const int*)lp;
    bool is64 = true;
    #pragma unroll
    for (int w = 1; w < 32; w += 2) is64 &= (L[w] == 0);
    return is64 ? (int)((const long long*)lp)[b] : L[b];
}

__device__ __forceinline__ void cpa16(unsigned int dst, const void* src) {
    asm volatile("cp.async.cg.shared.global [%0], [%1], 16;" :: "r"(dst), "l"(src));
}
#define CPA_COMMIT() asm volatile("cp.async.commit_group;")
#define CPA_WAIT0()  asm volatile("cp.async.wait_group 0;")

__device__ __forceinline__ unsigned int smem_u32(const void* p) {
    unsigned int a;
    asm("{ .reg .u64 t; cvta.to.shared.u64 t, %1; cvt.u32.u64 %0, t; }" : "=r"(a) : "l"(p));
    return a;
}

__global__ void __launch_bounds__(NTHR, 1)
lstm_persistent(const float* __restrict__ x,
                const void* __restrict__ length,
                const float* __restrict__ Wih0, const float* __restrict__ Whh0,
                const float* __restrict__ b0v,
                const float* __restrict__ Wih1, const float* __restrict__ Whh1,
                const float* __restrict__ b1v)
{
    extern __shared__ float smem[];
    float* z_x     = smem + ZX_OFF;
    float* z_h     = smem + ZH_OFF;
    float* W_s     = smem + W_OFF;
    float* gates_s = smem + G_OFF;
    const unsigned int zx_u = smem_u32(z_x);
    const unsigned int zh_u = smem_u32(z_h);

    const int tid   = threadIdx.x;
    const int hbase = blockIdx.x * NH;

    const int c   = tid & 15;              // gate column (c = hh*4 + gate)
    const int bh  = (tid >> 4) & 1;
    const int bg  = (tid >> 5) & 3;
    const int kh  = tid >> 7;              // k-half within each 512-K block
    const int b0i = bg*8 + bh*4;           // 4 batch rows per thread

    const int eb  = tid & 31;              // elementwise mapping (tid<128)
    const int ehh = tid >> 5;
    int lb = 0;
    if (tid < 128) lb = load_length(length, eb);

    for (int layer = 0; layer < 2; ++layer) {
        const float* Wih  = layer ? Wih1 : Wih0;
        const float* Whh  = layer ? Whh1 : Whh0;
        const float* bias = layer ? b1v  : b0v;
        const float* xbase = layer ? (g_hA + ROWSZ) : x;
        float* hbuf = layer ? g_hB : g_hA;

        // Stage weights: W_s[(k>>2)*64 + c*4 + (k&3)] = W[k][col(c)]
        __syncthreads();
        for (int i = tid; i < 1024*NC; i += NTHR) {
            int k  = i >> 4;
            int cc = i & 15;
            int col = ((cc & 3) << 9) + hbase + (cc >> 2);
            float w = (k < FEATD) ? Wih[(size_t)k*NCOL4 + col]
                                  : Whh[(size_t)(k-FEATD)*NCOL4 + col];
            W_s[((k >> 2) << 6) + (cc << 2) + (k & 3)] = w;
        }
        float bv = bias[((c & 3) << 9) + hbase + (c >> 2)];

        // load x(0) into z_x (padded rows)
        {
            const float* xrow = xbase;
            #pragma unroll
            for (int j = 0; j < 16; ++j) {
                int i = tid + j*NTHR;
                int b = i >> 7, k4 = i & 127;
                cpa16(zx_u + (b*ZS + (k4 << 2))*4, xrow + b*512 + (k4 << 2));
            }
            CPA_COMMIT();
        }
        CPA_WAIT0();
        __syncthreads();

        float creg = 0.f, hreg = 0.f;

        for (int t = 0; t < TT; ++t) {
            // 1) stage h(t) asynchronously; awaited after the x-GEMM
            {
                const float* hrow = hbuf + (size_t)t*ROWSZ;
                #pragma unroll
                for (int j = 0; j < 16; ++j) {
                    int i = tid + j*NTHR;
                    int b = i >> 7, k4 = i & 127;
                    cpa16(zh_u + (b*ZS + (k4 << 2))*4, hrow + b*512 + (k4 << 2));
                }
                CPA_COMMIT();
            }

            // 2) prefetch x(t+1) into registers (latency hidden by x-GEMM)
            float4 xp[16];
            {
                int tn = (t + 1 < TT) ? (t + 1) : (TT - 1);
                const float4* xnext = (const float4*)(xbase + (size_t)tn*ROWSZ);
                #pragma unroll
                for (int j = 0; j < 16; ++j)
                    xp[j] = __ldcg(xnext + tid + j*NTHR);
            }

            float a0 = 0.f, a1 = 0.f, a2 = 0.f, a3 = 0.f;

            // 3) x-GEMM: k in [0,512), this thread kh*256..+256
            {
                const float* wp = W_s + ((kh*256) >> 2)*64 + (c << 2);
                const float* zp = z_x + b0i*ZS + kh*256;
                #pragma unroll 8
                for (int k4 = 0; k4 < 64; ++k4) {
                    float4 w  = *(const float4*)(wp + (k4 << 6));
                    float4 z0 = *(const float4*)(zp + (k4 << 2));
                    float4 z1 = *(const float4*)(zp + ZS   + (k4 << 2));
                    float4 z2 = *(const float4*)(zp + 2*ZS + (k4 << 2));
                    float4 z3 = *(const float4*)(zp + 3*ZS + (k4 << 2));
                    a0 += z0.x*w.x; a0 += z0.y*w.y; a0 += z0.z*w.z; a0 += z0.w*w.w;
                    a1 += z1.x*w.x; a1 += z1.y*w.y; a1 += z1.z*w.z; a1 += z1.w*w.w;
                    a2 += z2.x*w.x; a2 += z2.y*w.y; a2 += z2.z*w.z; a2 += z2.w*w.w;
                    a3 += z3.x*w.x; a3 += z3.y*w.y; a3 += z3.z*w.z; a3 += z3.w*w.w;
                }
            }

            // 4) h(t) must be resident; also closes all z_x reads of step t
            CPA_WAIT0();
            __syncthreads();

            // 5) store x(t+1) to z_x (all step-t reads completed at the sync)
            #pragma unroll
            for (int j = 0; j < 16; ++j) {
                int i = tid + j*NTHR;
                int b = i >> 7, k4 = i & 127;
                *(float4*)(z_x + b*ZS + (k4 << 2)) = xp[j];
            }

            // 6) h-GEMM: k in [512,1024)
            {
                const float* wp = W_s + ((512 + kh*256) >> 2)*64 + (c << 2);
                const float* zp = z_h + b0i*ZS + kh*256;
                #pragma unroll 8
                for (int k4 = 0; k4 < 64; ++k4) {
                    float4 w  = *(const float4*)(wp + (k4 << 6));
                    float4 z0 = *(const float4*)(zp + (k4 << 2));
                    float4 z1 = *(const float4*)(zp + ZS   + (k4 << 2));
                    float4 z2 = *(const float4*)(zp + 2*ZS + (k4 << 2));
                    float4 z3 = *(const float4*)(zp + 3*ZS + (k4 << 2));
                    a0 += z0.x*w.x; a0 += z0.y*w.y; a0 += z0.z*w.z; a0 += z0.w*w.w;
                    a1 += z1.x*w.x; a1 += z1.y*w.y; a1 += z1.z*w.z; a1 += z1.w*w.w;
                    a2 += z2.x*w.x; a2 += z2.y*w.y; a2 += z2.z*w.z; a2 += z2.w*w.w;
                    a3 += z3.x*w.x; a3 += z3.y*w.y; a3 += z3.z*w.z; a3 += z3.w*w.w;
                }
            }

            // 7) cross-kh reduce via smem
            if (kh == 1) {
                gates_s[(b0i+0)*17 + c] = a0;
                gates_s[(b0i+1)*17 + c] = a1;
                gates_s[(b0i+2)*17 + c] = a2;
                gates_s[(b0i+3)*17 + c] = a3;
            }
            __syncthreads();
            if (kh == 0) {
                gates_s[(b0i+0)*17 + c] += a0 + bv;
                gates_s[(b0i+1)*17 + c] += a1 + bv;
                gates_s[(b0i+2)*17 + c] += a2 + bv;
                gates_s[(b0i+3)*17 + c] += a3 + bv;
            }
            __syncthreads();

            // 8) LSTM elementwise: thread owns (b, hidden) state
            if (tid < 128) {
                float fg = gates_s[eb*17 + ehh*4 + 0];
                float ig = gates_s[eb*17 + ehh*4 + 1];
                float og = gates_s[eb*17 + ehh*4 + 2];
                float gg = gates_s[eb*17 + ehh*4 + 3];
                float cn, hn;
                if (t < lb) {
                    float sf = __fdividef(1.f, 1.f + __expf(-fg));
                    float si = __fdividef(1.f, 1.f + __expf(-ig));
                    float so = __fdividef(1.f, 1.f + __expf(-og));
                    float tg = 2.f*__fdividef(1.f, 1.f + __expf(-2.f*gg)) - 1.f;
                    cn = sf*creg + si*tg;
                    float tc = 2.f*__fdividef(1.f, 1.f + __expf(-2.f*cn)) - 1.f;
                    hn = so*tc;
                } else {
                    cn = creg;
                    hn = hreg;
                }
                creg = cn;
                hreg = hn;
                hbuf[(size_t)(t+1)*ROWSZ + eb*HIDD + hbase + ehh] = hn;
            }
            grid_barrier();
        }
    }
}

// out[r][a] = h1[r] . Wfc[:,a] + bfc[a],  h1 row = g_hB row r+32
__global__ void __launch_bounds__(256)
fc_kernel(const float* __restrict__ Wfc, const float* __restrict__ bfc,
          float* __restrict__ out)
{
    __shared__ float w_s[128*64];
    __shared__ float h_s[32*128];
    const int tid = threadIdx.x;
    const int rbase = blockIdx.x * 32;
    const int a  = tid & 63;
    const int r4 = tid >> 6;

    float acc[8];
    float bvv = bfc[a];
    #pragma unroll
    for (int j = 0; j < 8; ++j) acc[j] = bvv;

    for (int kc = 0; kc < 512; kc += 128) {
        __syncthreads();
        for (int i = tid; i < 128*64/4; i += 256)
            ((float4*)w_s)[i] = ((const float4*)(Wfc + (size_t)kc*64))[i];
        for (int i = tid; i < 32*128/4; i += 256) {
            int r  = i >> 5;
            int k4 = i & 31;
            ((float4*)(h_s + r*128))[k4] =
                *(const float4*)(g_hB + (size_t)(rbase + r + BB)*HIDD + kc + (k4 << 2));
        }
        __syncthreads();
        #pragma unroll 4
        for (int k = 0; k < 128; ++k) {
            float w = w_s[(k << 6) + a];
            #pragma unroll
            for (int j = 0; j < 8; ++j)
                acc[j] += h_s[(r4 + 4*j)*128 + k] * w;
        }
    }
    #pragma unroll
    for (int j = 0; j < 8; ++j)
        out[(size_t)(rbase + r4 + 4*j)*64 + a] = acc[j];
}

extern "C" void kernel_launch(void* const* d_in, const int* in_sizes, int n_in,
                              void* d_out, int out_size)
{
    const float* x      = (const float*)d_in[0];
    const void*  length = (const void*)d_in[1];
    const float* Wih0   = (const float*)d_in[2];
    const float* Whh0   = (const float*)d_in[3];
    const float* b0v    = (const float*)d_in[4];
    const float* Wih1   = (const float*)d_in[5];
    const float* Whh1   = (const float*)d_in[6];
    const float* b1v    = (const float*)d_in[7];
    const float* Wfc    = (const float*)d_in[8];
    const float* bfc    = (const float*)d_in[9];
    float* out = (float*)d_out;

    const int smem_bytes = SMEM_FLOATS * (int)sizeof(float); // ~199.8 KB
    cudaFuncSetAttribute(lstm_persistent,
                         cudaFuncAttributeMaxDynamicSharedMemorySize, smem_bytes);

    lstm_persistent<<<NCTA, NTHR, smem_bytes>>>(x, length, Wih0, Whh0, b0v,
                                                Wih1, Whh1, b1v);
    fc_kernel<<<(TT*BB)/32, 256>>>(Wfc, bfc, out);
}

// round 10
// speedup vs baseline: 1.5404x; 1.0406x over previous
#include <cuda_runtime.h>

#define TT    2048
#define BB    32
#define FEATD 512
#define HIDD  512
#define NCOL4 2048
#define NCTA  128
#define NH    4
#define NC    16
#define NTHR  256
#define ROWSZ (BB*HIDD)      // 16384 floats per timestep of h

// smem layout (floats)
#define ZX_OFF   0            // z_x: [32][512]
#define ZH_OFF   16384        // z_h: [32][512]
#define W_OFF    32768        // W_s: 16384
#define G_OFF    49152        // gates: 32*17
#define SMEM_FLOATS (G_OFF + 32*17)   // ~194 KB

__device__ __align__(256) float g_hA[(TT+1)*ROWSZ];
__device__ __align__(256) float g_hB[(TT+1)*ROWSZ];
__device__ unsigned int g_grp[8] = {0,0,0,0,0,0,0,0};
__device__ unsigned int g_root  = 0;
__device__ unsigned int g_gen   = 0;

// Two-level tree grid barrier: 8 group counters x 16 CTAs, then root x 8.
// Parallel group arrivals cut same-address atomic serialization ~4x vs a
// single counter. All counters self-reset each barrier; g_gen is monotonic,
// so state is clean at every graph replay.
__device__ __forceinline__ void grid_barrier() {
    __threadfence();
    __syncthreads();
    if (threadIdx.x == 0) {
        volatile unsigned int* vgen = &g_gen;
        unsigned int gen = *vgen;
        int grp = blockIdx.x >> 4;
        if (atomicAdd(&g_grp[grp], 1u) == 15u) {
            atomicExch(&g_grp[grp], 0u);
            if (atomicAdd(&g_root, 1u) == 7u) {
                atomicExch(&g_root, 0u);
                __threadfence();
                atomicAdd(&g_gen, 1u);
            }
        }
        while (*vgen == gen) {}
    }
    __syncthreads();
}

// JAX silently downcasts int64->int32 unless x64 mode is on; detect at runtime.
__device__ __forceinline__ int load_length(const void* lp, int b) {
    const int* L = (const int*)lp;
    bool is64 = true;
    #pragma unroll
    for (int w = 1; w < 32; w += 2) is64 &= (L[w] == 0);
    return is64 ? (int)((const long long*)lp)[b] : L[b];
}

__device__ __forceinline__ void cpa16(unsigned int dst, const void* src) {
    asm volatile("cp.async.cg.shared.global [%0], [%1], 16;" :: "r"(dst), "l"(src));
}
#define CPA_COMMIT() asm volatile("cp.async.commit_group;")
#define CPA_WAIT0()  asm volatile("cp.async.wait_group 0;")

__device__ __forceinline__ unsigned int smem_u32(const void* p) {
    unsigned int a;
    asm("{ .reg .u64 t; cvta.to.shared.u64 t, %1; cvt.u32.u64 %0, t; }" : "=r"(a) : "l"(p));
    return a;
}

__global__ void __launch_bounds__(NTHR, 1)
lstm_persistent(const float* __restrict__ x,
                const void* __restrict__ length,
                const float* __restrict__ Wih0, const float* __restrict__ Whh0,
                const float* __restrict__ b0v,
                const float* __restrict__ Wih1, const float* __restrict__ Whh1,
                const float* __restrict__ b1v)
{
    extern __shared__ float smem[];
    float* z_x     = smem + ZX_OFF;
    float* z_h     = smem + ZH_OFF;
    float* W_s     = smem + W_OFF;
    float* gates_s = smem + G_OFF;
    const unsigned int zx_u = smem_u32(z_x);
    const unsigned int zh_u = smem_u32(z_h);

    const int tid   = threadIdx.x;
    const int hbase = blockIdx.x * NH;

    const int c   = tid & 15;              // gate column (c = hh*4 + gate)
    const int bh  = (tid >> 4) & 1;
    const int bg  = (tid >> 5) & 3;
    const int kh  = tid >> 7;              // k-half within each 512-K block
    const int b0i = bg*8 + bh*4;           // 4 batch rows per thread

    const int eb  = tid & 31;              // elementwise mapping (tid<128)
    const int ehh = tid >> 5;
    int lb = 0;
    if (tid < 128) lb = load_length(length, eb);

    for (int layer = 0; layer < 2; ++layer) {
        const float* Wih  = layer ? Wih1 : Wih0;
        const float* Whh  = layer ? Whh1 : Whh0;
        const float* bias = layer ? b1v  : b0v;
        const float* xbase = layer ? (g_hA + ROWSZ) : x;
        float* hbuf = layer ? g_hB : g_hA;

        // Stage weights: W_s[(k>>2)*64 + c*4 + (k&3)] = W[k][col(c)]
        __syncthreads();
        for (int i = tid; i < 1024*NC; i += NTHR) {
            int k  = i >> 4;
            int cc = i & 15;
            int col = ((cc & 3) << 9) + hbase + (cc >> 2);
            float w = (k < FEATD) ? Wih[(size_t)k*NCOL4 + col]
                                  : Whh[(size_t)(k-FEATD)*NCOL4 + col];
            W_s[((k >> 2) << 6) + (cc << 2) + (k & 3)] = w;
        }
        float bv = bias[((c & 3) << 9) + hbase + (c >> 2)];

        // load x(0) into z_x
        {
            const float* xrow = xbase;
            #pragma unroll
            for (int j = 0; j < 16; ++j) {
                int i = tid + j*NTHR;
                int b = i >> 7, k4 = i & 127;
                cpa16(zx_u + ((b << 9) + (k4 << 2))*4, xrow + b*512 + (k4 << 2));
            }
            CPA_COMMIT();
        }
        CPA_WAIT0();
        __syncthreads();

        float creg = 0.f, hreg = 0.f;

        for (int t = 0; t < TT; ++t) {
            // 1) stage h(t) asynchronously; awaited after the x-GEMM
            {
                const float* hrow = hbuf + (size_t)t*ROWSZ;
                #pragma unroll
                for (int j = 0; j < 16; ++j) {
                    int i = tid + j*NTHR;
                    int b = i >> 7, k4 = i & 127;
                    cpa16(zh_u + ((b << 9) + (k4 << 2))*4, hrow + b*512 + (k4 << 2));
                }
                CPA_COMMIT();
            }

            // 2) prefetch x(t+1) into registers (latency hidden by x-GEMM)
            float4 xp[16];
            {
                int tn = (t + 1 < TT) ? (t + 1) : (TT - 1);
                const float4* xnext = (const float4*)(xbase + (size_t)tn*ROWSZ);
                #pragma unroll
                for (int j = 0; j < 16; ++j)
                    xp[j] = __ldcg(xnext + tid + j*NTHR);
            }

            float a0 = 0.f, a1 = 0.f, a2 = 0.f, a3 = 0.f;

            // 3) x-GEMM: k in [0,512), this thread kh*256..+256
            {
                const float* wp = W_s + ((kh*256) >> 2)*64 + (c << 2);
                const float* zp = z_x + b0i*512 + kh*256;
                #pragma unroll 8
                for (int k4 = 0; k4 < 64; ++k4) {
                    float4 w  = *(const float4*)(wp + (k4 << 6));
                    float4 z0 = *(const float4*)(zp + (k4 << 2));
                    float4 z1 = *(const float4*)(zp + 512  + (k4 << 2));
                    float4 z2 = *(const float4*)(zp + 1024 + (k4 << 2));
                    float4 z3 = *(const float4*)(zp + 1536 + (k4 << 2));
                    a0 += z0.x*w.x; a0 += z0.y*w.y; a0 += z0.z*w.z; a0 += z0.w*w.w;
                    a1 += z1.x*w.x; a1 += z1.y*w.y; a1 += z1.z*w.z; a1 += z1.w*w.w;
                    a2 += z2.x*w.x; a2 += z2.y*w.y; a2 += z2.z*w.z; a2 += z2.w*w.w;
                    a3 += z3.x*w.x; a3 += z3.y*w.y; a3 += z3.z*w.z; a3 += z3.w*w.w;
                }
            }

            // 4) h(t) must be resident; also closes all z_x reads of step t
            CPA_WAIT0();
            __syncthreads();

            // 5) store x(t+1) to z_x (all step-t reads completed at the sync)
            #pragma unroll
            for (int j = 0; j < 16; ++j) {
                int i = tid + j*NTHR;
                int b = i >> 7, k4 = i & 127;
                *(float4*)(z_x + (b << 9) + (k4 << 2)) = xp[j];
            }

            // 6) h-GEMM: k in [512,1024)
            {
                const float* wp = W_s + ((512 + kh*256) >> 2)*64 + (c << 2);
                const float* zp = z_h + b0i*512 + kh*256;
                #pragma unroll 8
                for (int k4 = 0; k4 < 64; ++k4) {
                    float4 w  = *(const float4*)(wp + (k4 << 6));
                    float4 z0 = *(const float4*)(zp + (k4 << 2));
                    float4 z1 = *(const float4*)(zp + 512  + (k4 << 2));
                    float4 z2 = *(const float4*)(zp + 1024 + (k4 << 2));
                    float4 z3 = *(const float4*)(zp + 1536 + (k4 << 2));
                    a0 += z0.x*w.x; a0 += z0.y*w.y; a0 += z0.z*w.z; a0 += z0.w*w.w;
                    a1 += z1.x*w.x; a1 += z1.y*w.y; a1 += z1.z*w.z; a1 += z1.w*w.w;
                    a2 += z2.x*w.x; a2 += z2.y*w.y; a2 += z2.z*w.z; a2 += z2.w*w.w;
                    a3 += z3.x*w.x; a3 += z3.y*w.y; a3 += z3.z*w.z; a3 += z3.w*w.w;
                }
            }

            // 7) cross-kh reduce via smem
            if (kh == 1) {
                gates_s[(b0i+0)*17 + c] = a0;
                gates_s[(b0i+1)*17 + c] = a1;
                gates_s[(b0i+2)*17 + c] = a2;
                gates_s[(b0i+3)*17 + c] = a3;
            }
            __syncthreads();
            if (kh == 0) {
                gates_s[(b0i+0)*17 + c] += a0 + bv;
                gates_s[(b0i+1)*17 + c] += a1 + bv;
                gates_s[(b0i+2)*17 + c] += a2 + bv;
                gates_s[(b0i+3)*17 + c] += a3 + bv;
            }
            __syncthreads();

            // 8) LSTM elementwise: thread owns (b, hidden) state
            if (tid < 128) {
                float fg = gates_s[eb*17 + ehh*4 + 0];
                float ig = gates_s[eb*17 + ehh*4 + 1];
                float og = gates_s[eb*17 + ehh*4 + 2];
                float gg = gates_s[eb*17 + ehh*4 + 3];
                float cn, hn;
                if (t < lb) {
                    float sf = 1.f/(1.f + __expf(-fg));
                    float si = 1.f/(1.f + __expf(-ig));
                    float so = 1.f/(1.f + __expf(-og));
                    float tg = 2.f/(1.f + __expf(-2.f*gg)) - 1.f;
                    cn = sf*creg + si*tg;
                    float tc = 2.f/(1.f + __expf(-2.f*cn)) - 1.f;
                    hn = so*tc;
                } else {
                    cn = creg;
                    hn = hreg;
                }
                creg = cn;
                hreg = hn;
                hbuf[(size_t)(t+1)*ROWSZ + eb*HIDD + hbase + ehh] = hn;
            }
            grid_barrier();
        }
    }
}

// out[r][a] = h1[r] . Wfc[:,a] + bfc[a],  h1 row = g_hB row r+32
__global__ void __launch_bounds__(256)
fc_kernel(const float* __restrict__ Wfc, const float* __restrict__ bfc,
          float* __restrict__ out)
{
    __shared__ float w_s[128*64];
    __shared__ float h_s[32*128];
    const int tid = threadIdx.x;
    const int rbase = blockIdx.x * 32;
    const int a  = tid & 63;
    const int r4 = tid >> 6;

    float acc[8];
    float bvv = bfc[a];
    #pragma unroll
    for (int j = 0; j < 8; ++j) acc[j] = bvv;

    for (int kc = 0; kc < 512; kc += 128) {
        __syncthreads();
        for (int i = tid; i < 128*64/4; i += 256)
            ((float4*)w_s)[i] = ((const float4*)(Wfc + (size_t)kc*64))[i];
        for (int i = tid; i < 32*128/4; i += 256) {
            int r  = i >> 5;
            int k4 = i & 31;
            ((float4*)(h_s + r*128))[k4] =
                *(const float4*)(g_hB + (size_t)(rbase + r + BB)*HIDD + kc + (k4 << 2));
        }
        __syncthreads();
        #pragma unroll 4
        for (int k = 0; k < 128; ++k) {
            float w = w_s[(k << 6) + a];
            #pragma unroll
            for (int j = 0; j < 8; ++j)
                acc[j] += h_s[(r4 + 4*j)*128 + k] * w;
        }
    }
    #pragma unroll
    for (int j = 0; j < 8; ++j)
        out[(size_t)(rbase + r4 + 4*j)*64 + a] = acc[j];
}

extern "C" void kernel_launch(void* const* d_in, const int* in_sizes, int n_in,
                              void* d_out, int out_size)
{
    const float* x      = (const float*)d_in[0];
    const void*  length = (const void*)d_in[1];
    const float* Wih0   = (const float*)d_in[2];
    const float* Whh0   = (const float*)d_in[3];
    const float* b0v    = (const float*)d_in[4];
    const float* Wih1   = (const float*)d_in[5];
    const float* Whh1   = (const float*)d_in[6];
    const float* b1v    = (const float*)d_in[7];
    const float* Wfc    = (const float*)d_in[8];
    const float* bfc    = (const float*)d_in[9];
    float* out = (float*)d_out;

    const int smem_bytes = SMEM_FLOATS * (int)sizeof(float); // ~194 KB
    cudaFuncSetAttribute(lstm_persistent,
                         cudaFuncAttributeMaxDynamicSharedMemorySize, smem_bytes);

    lstm_persistent<<<NCTA, NTHR, smem_bytes>>>(x, length, Wih0, Whh0, b0v,
                                                Wih1, Whh1, b1v);
    fc_kernel<<<(TT*BB)/32, 256>>>(Wfc, bfc, out);
}

// round 11
// speedup vs baseline: 1.7599x; 1.1425x over previous
#include <cuda_runtime.h>

#define TT    2048
#define BB    32
#define FEATD 512
#define HIDD  512
#define NCOL4 2048
#define NCTA  128
#define NH    4
#define NC    16
#define NTHR  256
#define ROWSZ (BB*HIDD)      // 16384 floats per timestep of h

// smem layout (floats)
#define ZX_OFF   0            // z_x: [32][512]
#define ZH_OFF   16384        // z_h: [32][512]
#define W_OFF    32768        // W_s: 16384
#define G_OFF    49152        // gates: 32*17
#define SMEM_FLOATS (G_OFF + 32*17)   // ~194 KB

__device__ __align__(256) float g_hA[(TT+1)*ROWSZ];
__device__ __align__(256) float g_hB[(TT+1)*ROWSZ];
__device__ unsigned int g_count = 0;
__device__ unsigned int g_gen   = 0;

// JAX silently downcasts int64->int32 unless x64 mode is on; detect at runtime.
__device__ __forceinline__ int load_length(const void* lp, int b) {
    const int* L = (const int*)lp;
    bool is64 = true;
    #pragma unroll
    for (int w = 1; w < 32; w += 2) is64 &= (L[w] == 0);
    return is64 ? (int)((const long long*)lp)[b] : L[b];
}

__device__ __forceinline__ void cpa16(unsigned int dst, const void* src) {
    asm volatile("cp.async.cg.shared.global [%0], [%1], 16;" :: "r"(dst), "l"(src));
}
#define CPA_COMMIT() asm volatile("cp.async.commit_group;")
#define CPA_WAIT0()  asm volatile("cp.async.wait_group 0;")

__device__ __forceinline__ unsigned int smem_u32(const void* p) {
    unsigned int a;
    asm("{ .reg .u64 t; cvta.to.shared.u64 t, %1; cvt.u32.u64 %0, t; }" : "=r"(a) : "l"(p));
    return a;
}

// Split grid barrier (single-counter, R6-proven atomics).
// arrive: non-blocking; last arriver resets count and bumps gen (monotonic
// across graph replays -> launch state always clean).
__device__ __forceinline__ void grid_arrive() {
    __threadfence();
    __syncthreads();
    if (threadIdx.x == 0) {
        if (atomicAdd(&g_count, 1u) == NCTA - 1u) {
            atomicExch(&g_count, 0u);
            __threadfence();
            atomicAdd(&g_gen, 1u);
        }
    }
}
// wait: block until gen reaches target (wrap-safe compare).
__device__ __forceinline__ void grid_wait(unsigned int target) {
    if (threadIdx.x == 0) {
        volatile unsigned int* vg = &g_gen;
        while ((int)(*vg - target) < 0) {}
    }
    __syncthreads();
}

__global__ void __launch_bounds__(NTHR, 1)
lstm_persistent(const float* __restrict__ x,
                const void* __restrict__ length,
                const float* __restrict__ Wih0, const float* __restrict__ Whh0,
                const float* __restrict__ b0v,
                const float* __restrict__ Wih1, const float* __restrict__ Whh1,
                const float* __restrict__ b1v)
{
    extern __shared__ float smem[];
    float* z_x     = smem + ZX_OFF;
    float* z_h     = smem + ZH_OFF;
    float* W_s     = smem + W_OFF;
    float* gates_s = smem + G_OFF;
    const unsigned int zx_u = smem_u32(z_x);
    const unsigned int zh_u = smem_u32(z_h);

    const int tid   = threadIdx.x;
    const int hbase = blockIdx.x * NH;

    // gen base at launch: stable until every CTA has arrived at barrier 0.
    const unsigned int bar_base = *((volatile unsigned int*)&g_gen);

    const int c   = tid & 15;              // gate column (c = hh*4 + gate)
    const int bh  = (tid >> 4) & 1;
    const int bg  = (tid >> 5) & 3;
    const int kh  = tid >> 7;              // k-half within each 512-K block
    const int b0i = bg*8 + bh*4;           // 4 batch rows per thread

    const int eb  = tid & 31;              // elementwise mapping (tid<128)
    const int ehh = tid >> 5;
    int lb = 0;
    if (tid < 128) lb = load_length(length, eb);

    for (int layer = 0; layer < 2; ++layer) {
        const float* Wih  = layer ? Wih1 : Wih0;
        const float* Whh  = layer ? Whh1 : Whh0;
        const float* bias = layer ? b1v  : b0v;
        const float* xbase = layer ? (g_hA + ROWSZ) : x;
        float* hbuf = layer ? g_hB : g_hA;

        // Stage weights: W_s[(k>>2)*64 + c*4 + (k&3)] = W[k][col(c)]
        __syncthreads();
        for (int i = tid; i < 1024*NC; i += NTHR) {
            int k  = i >> 4;
            int cc = i & 15;
            int col = ((cc & 3) << 9) + hbase + (cc >> 2);
            float w = (k < FEATD) ? Wih[(size_t)k*NCOL4 + col]
                                  : Whh[(size_t)(k-FEATD)*NCOL4 + col];
            W_s[((k >> 2) << 6) + (cc << 2) + (k & 3)] = w;
        }
        float bv = bias[((c & 3) << 9) + hbase + (c >> 2)];

        // load x(0) into z_x  (layer 1: g_hA row 1, visible since this CTA
        // already observed gen >= bar_base+TT-1 during layer 0)
        {
            const float* xrow = xbase;
            #pragma unroll
            for (int j = 0; j < 16; ++j) {
                int i = tid + j*NTHR;
                int b = i >> 7, k4 = i & 127;
                cpa16(zx_u + ((b << 9) + (k4 << 2))*4, xrow + b*512 + (k4 << 2));
            }
            CPA_COMMIT();
        }
        CPA_WAIT0();
        __syncthreads();

        float creg = 0.f, hreg = 0.f;

        for (int t = 0; t < TT; ++t) {
            // 1) prefetch x(t+1) into registers (latency hidden by x-GEMM)
            float4 xp[16];
            {
                int tn = (t + 1 < TT) ? (t + 1) : (TT - 1);
                const float4* xnext = (const float4*)(xbase + (size_t)tn*ROWSZ);
                #pragma unroll
                for (int j = 0; j < 16; ++j)
                    xp[j] = __ldcg(xnext + tid + j*NTHR);
            }

            float a0 = 0.f, a1 = 0.f, a2 = 0.f, a3 = 0.f;

            // 2) x-GEMM: k in [0,512) — needs no h(t); hides barrier wait
            {
                const float* wp = W_s + ((kh*256) >> 2)*64 + (c << 2);
                const float* zp = z_x + b0i*512 + kh*256;
                #pragma unroll 8
                for (int k4 = 0; k4 < 64; ++k4) {
                    float4 w  = *(const float4*)(wp + (k4 << 6));
                    float4 z0 = *(const float4*)(zp + (k4 << 2));
                    float4 z1 = *(const float4*)(zp + 512  + (k4 << 2));
                    float4 z2 = *(const float4*)(zp + 1024 + (k4 << 2));
                    float4 z3 = *(const float4*)(zp + 1536 + (k4 << 2));
                    a0 += z0.x*w.x; a0 += z0.y*w.y; a0 += z0.z*w.z; a0 += z0.w*w.w;
                    a1 += z1.x*w.x; a1 += z1.y*w.y; a1 += z1.z*w.z; a1 += z1.w*w.w;
                    a2 += z2.x*w.x; a2 += z2.y*w.y; a2 += z2.z*w.z; a2 += z2.w*w.w;
                    a3 += z3.x*w.x; a3 += z3.y*w.y; a3 += z3.z*w.z; a3 += z3.w*w.w;
                }
            }

            // 3) barrier wait for h(t) visibility (normally already satisfied)
            grid_wait(bar_base + (unsigned)(layer*TT + t));

            // 4) stage h(t) (async); store x(t+1) to z_x meanwhile
            {
                const float* hrow = hbuf + (size_t)t*ROWSZ;
                #pragma unroll
                for (int j = 0; j < 16; ++j) {
                    int i = tid + j*NTHR;
                    int b = i >> 7, k4 = i & 127;
                    cpa16(zh_u + ((b << 9) + (k4 << 2))*4, hrow + b*512 + (k4 << 2));
                }
                CPA_COMMIT();
            }
            #pragma unroll
            for (int j = 0; j < 16; ++j) {
                int i = tid + j*NTHR;
                int b = i >> 7, k4 = i & 127;
                *(float4*)(z_x + (b << 9) + (k4 << 2)) = xp[j];
            }

            // 5) h resident
            CPA_WAIT0();
            __syncthreads();

            // 6) h-GEMM: k in [512,1024)
            {
                const float* wp = W_s + ((512 + kh*256) >> 2)*64 + (c << 2);
                const float* zp = z_h + b0i*512 + kh*256;
                #pragma unroll 8
                for (int k4 = 0; k4 < 64; ++k4) {
                    float4 w  = *(const float4*)(wp + (k4 << 6));
                    float4 z0 = *(const float4*)(zp + (k4 << 2));
                    float4 z1 = *(const float4*)(zp + 512  + (k4 << 2));
                    float4 z2 = *(const float4*)(zp + 1024 + (k4 << 2));
                    float4 z3 = *(const float4*)(zp + 1536 + (k4 << 2));
                    a0 += z0.x*w.x; a0 += z0.y*w.y; a0 += z0.z*w.z; a0 += z0.w*w.w;
                    a1 += z1.x*w.x; a1 += z1.y*w.y; a1 += z1.z*w.z; a1 += z1.w*w.w;
                    a2 += z2.x*w.x; a2 += z2.y*w.y; a2 += z2.z*w.z; a2 += z2.w*w.w;
                    a3 += z3.x*w.x; a3 += z3.y*w.y; a3 += z3.z*w.z; a3 += z3.w*w.w;
                }
            }

            // 7) cross-kh reduce via smem
            if (kh == 1) {
                gates_s[(b0i+0)*17 + c] = a0;
                gates_s[(b0i+1)*17 + c] = a1;
                gates_s[(b0i+2)*17 + c] = a2;
                gates_s[(b0i+3)*17 + c] = a3;
            }
            __syncthreads();
            if (kh == 0) {
                gates_s[(b0i+0)*17 + c] += a0 + bv;
                gates_s[(b0i+1)*17 + c] += a1 + bv;
                gates_s[(b0i+2)*17 + c] += a2 + bv;
                gates_s[(b0i+3)*17 + c] += a3 + bv;
            }
            __syncthreads();

            // 8) LSTM elementwise: thread owns (b, hidden) state
            if (tid < 128) {
                float fg = gates_s[eb*17 + ehh*4 + 0];
                float ig = gates_s[eb*17 + ehh*4 + 1];
                float og = gates_s[eb*17 + ehh*4 + 2];
                float gg = gates_s[eb*17 + ehh*4 + 3];
                float cn, hn;
                if (t < lb) {
                    float sf = 1.f/(1.f + __expf(-fg));
                    float si = 1.f/(1.f + __expf(-ig));
                    float so = 1.f/(1.f + __expf(-og));
                    float tg = 2.f/(1.f + __expf(-2.f*gg)) - 1.f;
                    cn = sf*creg + si*tg;
                    float tc = 2.f/(1.f + __expf(-2.f*cn)) - 1.f;
                    hn = so*tc;
                } else {
                    cn = creg;
                    hn = hreg;
                }
                creg = cn;
                hreg = hn;
                hbuf[(size_t)(t+1)*ROWSZ + eb*HIDD + hbase + ehh] = hn;
            }

            // 9) arrive only; the wait is overlapped with next step's x-GEMM
            grid_arrive();
        }
    }
}

// out[r][a] = h1[r] . Wfc[:,a] + bfc[a],  h1 row = g_hB row r+32
__global__ void __launch_bounds__(256)
fc_kernel(const float* __restrict__ Wfc, const float* __restrict__ bfc,
          float* __restrict__ out)
{
    __shared__ float w_s[128*64];
    __shared__ float h_s[32*128];
    const int tid = threadIdx.x;
    const int rbase = blockIdx.x * 32;
    const int a  = tid & 63;
    const int r4 = tid >> 6;

    float acc[8];
    float bvv = bfc[a];
    #pragma unroll
    for (int j = 0; j < 8; ++j) acc[j] = bvv;

    for (int kc = 0; kc < 512; kc += 128) {
        __syncthreads();
        for (int i = tid; i < 128*64/4; i += 256)
            ((float4*)w_s)[i] = ((const float4*)(Wfc + (size_t)kc*64))[i];
        for (int i = tid; i < 32*128/4; i += 256) {
            int r  = i >> 5;
            int k4 = i & 31;
            ((float4*)(h_s + r*128))[k4] =
                *(const float4*)(g_hB + (size_t)(rbase + r + BB)*HIDD + kc + (k4 << 2));
        }
        __syncthreads();
        #pragma unroll 4
        for (int k = 0; k < 128; ++k) {
            float w = w_s[(k << 6) + a];
            #pragma unroll
            for (int j = 0; j < 8; ++j)
                acc[j] += h_s[(r4 + 4*j)*128 + k] * w;
        }
    }
    #pragma unroll
    for (int j = 0; j < 8; ++j)
        out[(size_t)(rbase + r4 + 4*j)*64 + a] = acc[j];
}

extern "C" void kernel_launch(void* const* d_in, const int* in_sizes, int n_in,
                              void* d_out, int out_size)
{
    const float* x      = (const float*)d_in[0];
    const void*  length = (const void*)d_in[1];
    const float* Wih0   = (const float*)d_in[2];
    const float* Whh0   = (const float*)d_in[3];
    const float* b0v    = (const float*)d_in[4];
    const float* Wih1   = (const float*)d_in[5];
    const float* Whh1   = (const float*)d_in[6];
    const float* b1v    = (const float*)d_in[7];
    const float* Wfc    = (const float*)d_in[8];
    const float* bfc    = (const float*)d_in[9];
    float* out = (float*)d_out;

    const int smem_bytes = SMEM_FLOATS * (int)sizeof(float); // ~194 KB
    cudaFuncSetAttribute(lstm_persistent,
                         cudaFuncAttributeMaxDynamicSharedMemorySize, smem_bytes);

    lstm_persistent<<<NCTA, NTHR, smem_bytes>>>(x, length, Wih0, Whh0, b0v,
                                                Wih1, Whh1, b1v);
    fc_kernel<<<(TT*BB)/32, 256>>>(Wfc, bfc, out);
}

// round 12
// speedup vs baseline: 1.7818x; 1.0124x over previous
#include <cuda_runtime.h>

#define TT    2048
#define BB    32
#define FEATD 512
#define HIDD  512
#define NCOL4 2048
#define NCTA  128
#define NH    4
#define NC    16
#define NTHR  256
#define ROWSZ (BB*HIDD)      // 16384 floats per timestep of h

// smem layout (floats)
#define ZX_OFF   0            // z_x: [32][512]
#define ZH_OFF   16384        // z_h: [32][512]
#define W_OFF    32768        // W_s: 16384
#define G_OFF    49152        // gates: 32*17
#define SMEM_FLOATS (G_OFF + 32*17)   // ~194 KB

__device__ __align__(256) float g_hA[(TT+1)*ROWSZ];
__device__ __align__(256) float g_hB[(TT+1)*ROWSZ];
__device__ unsigned int g_count = 0;
__device__ unsigned int g_gen   = 0;

// JAX silently downcasts int64->int32 unless x64 mode is on; detect at runtime.
__device__ __forceinline__ int load_length(const void* lp, int b) {
    const int* L = (const int*)lp;
    bool is64 = true;
    #pragma unroll
    for (int w = 1; w < 32; w += 2) is64 &= (L[w] == 0);
    return is64 ? (int)((const long long*)lp)[b] : L[b];
}

__device__ __forceinline__ void cpa16(unsigned int dst, const void* src) {
    asm volatile("cp.async.cg.shared.global [%0], [%1], 16;" :: "r"(dst), "l"(src));
}
#define CPA_COMMIT() asm volatile("cp.async.commit_group;")
#define CPA_WAIT0()  asm volatile("cp.async.wait_group 0;")

__device__ __forceinline__ unsigned int smem_u32(const void* p) {
    unsigned int a;
    asm("{ .reg .u64 t; cvta.to.shared.u64 t, %1; cvt.u32.u64 %0, t; }" : "=r"(a) : "l"(p));
    return a;
}

// Split grid barrier (single-counter, R6-proven atomics).
// arrive: non-blocking; last arriver resets count and bumps gen (monotonic
// across graph replays -> launch state always clean).
__device__ __forceinline__ void grid_arrive() {
    __threadfence();
    __syncthreads();
    if (threadIdx.x == 0) {
        if (atomicAdd(&g_count, 1u) == NCTA - 1u) {
            atomicExch(&g_count, 0u);
            __threadfence();
            atomicAdd(&g_gen, 1u);
        }
    }
}
// wait: block until gen reaches target (wrap-safe compare).
__device__ __forceinline__ void grid_wait(unsigned int target) {
    if (threadIdx.x == 0) {
        volatile unsigned int* vg = &g_gen;
        while ((int)(*vg - target) < 0) {}
    }
    __syncthreads();
}

__global__ void __launch_bounds__(NTHR, 1)
lstm_persistent(const float* __restrict__ x,
                const void* __restrict__ length,
                const float* __restrict__ Wih0, const float* __restrict__ Whh0,
                const float* __restrict__ b0v,
                const float* __restrict__ Wih1, const float* __restrict__ Whh1,
                const float* __restrict__ b1v)
{
    extern __shared__ float smem[];
    float* z_x     = smem + ZX_OFF;
    float* z_h     = smem + ZH_OFF;
    float* W_s     = smem + W_OFF;
    float* gates_s = smem + G_OFF;
    const unsigned int zx_u = smem_u32(z_x);
    const unsigned int zh_u = smem_u32(z_h);

    const int tid   = threadIdx.x;
    const int hbase = blockIdx.x * NH;

    // gen base at launch: stable until every CTA has arrived at barrier 0.
    const unsigned int bar_base = *((volatile unsigned int*)&g_gen);

    const int c   = tid & 15;              // gate column (c = hh*4 + gate)
    const int bh  = (tid >> 4) & 1;
    const int bg  = (tid >> 5) & 3;
    const int kh  = tid >> 7;              // k-half within each 512-K block
    const int b0i = bg*8 + bh*4;           // 4 batch rows per thread

    const int eb  = tid & 31;              // elementwise mapping (tid<128)
    const int ehh = tid >> 5;
    int lb = 0;
    if (tid < 128) lb = load_length(length, eb);

    for (int layer = 0; layer < 2; ++layer) {
        const float* Wih  = layer ? Wih1 : Wih0;
        const float* Whh  = layer ? Whh1 : Whh0;
        const float* bias = layer ? b1v  : b0v;
        const float* xbase = layer ? (g_hA + ROWSZ) : x;
        float* hbuf = layer ? g_hB : g_hA;

        // Stage weights: W_s[(k>>2)*64 + c*4 + (k&3)] = W[k][col(c)]
        __syncthreads();
        for (int i = tid; i < 1024*NC; i += NTHR) {
            int k  = i >> 4;
            int cc = i & 15;
            int col = ((cc & 3) << 9) + hbase + (cc >> 2);
            float w = (k < FEATD) ? Wih[(size_t)k*NCOL4 + col]
                                  : Whh[(size_t)(k-FEATD)*NCOL4 + col];
            W_s[((k >> 2) << 6) + (cc << 2) + (k & 3)] = w;
        }
        float bv = bias[((c & 3) << 9) + hbase + (c >> 2)];

        // load x(0) into z_x  (layer 1: g_hA row 1, visible since this CTA
        // already observed gen >= bar_base+TT-1 during layer 0)
        {
            const float* xrow = xbase;
            #pragma unroll
            for (int j = 0; j < 16; ++j) {
                int i = tid + j*NTHR;
                int b = i >> 7, k4 = i & 127;
                cpa16(zx_u + ((b << 9) + (k4 << 2))*4, xrow + b*512 + (k4 << 2));
            }
            CPA_COMMIT();
        }
        CPA_WAIT0();
        __syncthreads();

        float creg = 0.f, hreg = 0.f;

        for (int t = 0; t < TT; ++t) {
            // 1) prefetch x(t+1) into registers (latency hidden by x-GEMM)
            float4 xp[16];
            {
                int tn = (t + 1 < TT) ? (t + 1) : (TT - 1);
                const float4* xnext = (const float4*)(xbase + (size_t)tn*ROWSZ);
                #pragma unroll
                for (int j = 0; j < 16; ++j)
                    xp[j] = __ldcg(xnext + tid + j*NTHR);
            }

            float a0 = 0.f, a1 = 0.f, a2 = 0.f, a3 = 0.f;

            const float* wpx = W_s + ((kh*256) >> 2)*64 + (c << 2);
            const float* zpx = z_x + b0i*512 + kh*256;

            // 2a) x-GEMM half 1: k4 in [0,32) — absorbs CTA skew
            #pragma unroll 8
            for (int k4 = 0; k4 < 32; ++k4) {
                float4 w  = *(const float4*)(wpx + (k4 << 6));
                float4 z0 = *(const float4*)(zpx + (k4 << 2));
                float4 z1 = *(const float4*)(zpx + 512  + (k4 << 2));
                float4 z2 = *(const float4*)(zpx + 1024 + (k4 << 2));
                float4 z3 = *(const float4*)(zpx + 1536 + (k4 << 2));
                a0 += z0.x*w.x; a0 += z0.y*w.y; a0 += z0.z*w.z; a0 += z0.w*w.w;
                a1 += z1.x*w.x; a1 += z1.y*w.y; a1 += z1.z*w.z; a1 += z1.w*w.w;
                a2 += z2.x*w.x; a2 += z2.y*w.y; a2 += z2.z*w.z; a2 += z2.w*w.w;
                a3 += z3.x*w.x; a3 += z3.y*w.y; a3 += z3.z*w.z; a3 += z3.w*w.w;
            }

            // 3) wait for h(t) visibility (usually already satisfied), then
            //    issue h staging so its transfer hides under x-GEMM half 2
            grid_wait(bar_base + (unsigned)(layer*TT + t));
            {
                const float* hrow = hbuf + (size_t)t*ROWSZ;
                #pragma unroll
                for (int j = 0; j < 16; ++j) {
                    int i = tid + j*NTHR;
                    int b = i >> 7, k4 = i & 127;
                    cpa16(zh_u + ((b << 9) + (k4 << 2))*4, hrow + b*512 + (k4 << 2));
                }
                CPA_COMMIT();
            }

            // 2b) x-GEMM half 2: k4 in [32,64)
            #pragma unroll 8
            for (int k4 = 32; k4 < 64; ++k4) {
                float4 w  = *(const float4*)(wpx + (k4 << 6));
                float4 z0 = *(const float4*)(zpx + (k4 << 2));
                float4 z1 = *(const float4*)(zpx + 512  + (k4 << 2));
                float4 z2 = *(const float4*)(zpx + 1024 + (k4 << 2));
                float4 z3 = *(const float4*)(zpx + 1536 + (k4 << 2));
                a0 += z0.x*w.x; a0 += z0.y*w.y; a0 += z0.z*w.z; a0 += z0.w*w.w;
                a1 += z1.x*w.x; a1 += z1.y*w.y; a1 += z1.z*w.z; a1 += z1.w*w.w;
                a2 += z2.x*w.x; a2 += z2.y*w.y; a2 += z2.z*w.z; a2 += z2.w*w.w;
                a3 += z3.x*w.x; a3 += z3.y*w.y; a3 += z3.z*w.z; a3 += z3.w*w.w;
            }

            // 4) h resident + all z_x reads of step t closed
            CPA_WAIT0();
            __syncthreads();

            // 5) store x(t+1) to z_x (overlaps with h-GEMM issue below)
            #pragma unroll
            for (int j = 0; j < 16; ++j) {
                int i = tid + j*NTHR;
                int b = i >> 7, k4 = i & 127;
                *(float4*)(z_x + (b << 9) + (k4 << 2)) = xp[j];
            }

            // 6) h-GEMM: k in [512,1024)
            {
                const float* wp = W_s + ((512 + kh*256) >> 2)*64 + (c << 2);
                const float* zp = z_h + b0i*512 + kh*256;
                #pragma unroll 8
                for (int k4 = 0; k4 < 64; ++k4) {
                    float4 w  = *(const float4*)(wp + (k4 << 6));
                    float4 z0 = *(const float4*)(zp + (k4 << 2));
                    float4 z1 = *(const float4*)(zp + 512  + (k4 << 2));
                    float4 z2 = *(const float4*)(zp + 1024 + (k4 << 2));
                    float4 z3 = *(const float4*)(zp + 1536 + (k4 << 2));
                    a0 += z0.x*w.x; a0 += z0.y*w.y; a0 += z0.z*w.z; a0 += z0.w*w.w;
                    a1 += z1.x*w.x; a1 += z1.y*w.y; a1 += z1.z*w.z; a1 += z1.w*w.w;
                    a2 += z2.x*w.x; a2 += z2.y*w.y; a2 += z2.z*w.z; a2 += z2.w*w.w;
                    a3 += z3.x*w.x; a3 += z3.y*w.y; a3 += z3.z*w.z; a3 += z3.w*w.w;
                }
            }

            // 7) cross-kh reduce via smem
            if (kh == 1) {
                gates_s[(b0i+0)*17 + c] = a0;
                gates_s[(b0i+1)*17 + c] = a1;
                gates_s[(b0i+2)*17 + c] = a2;
                gates_s[(b0i+3)*17 + c] = a3;
            }
            __syncthreads();
            if (kh == 0) {
                gates_s[(b0i+0)*17 + c] += a0 + bv;
                gates_s[(b0i+1)*17 + c] += a1 + bv;
                gates_s[(b0i+2)*17 + c] += a2 + bv;
                gates_s[(b0i+3)*17 + c] += a3 + bv;
            }
            __syncthreads();

            // 8) LSTM elementwise: thread owns (b, hidden) state
            if (tid < 128) {
                float fg = gates_s[eb*17 + ehh*4 + 0];
                float ig = gates_s[eb*17 + ehh*4 + 1];
                float og = gates_s[eb*17 + ehh*4 + 2];
                float gg = gates_s[eb*17 + ehh*4 + 3];
                float cn, hn;
                if (t < lb) {
                    float sf = 1.f/(1.f + __expf(-fg));
                    float si = 1.f/(1.f + __expf(-ig));
                    float so = 1.f/(1.f + __expf(-og));
                    float tg = 2.f/(1.f + __expf(-2.f*gg)) - 1.f;
                    cn = sf*creg + si*tg;
                    float tc = 2.f/(1.f + __expf(-2.f*cn)) - 1.f;
                    hn = so*tc;
                } else {
                    cn = creg;
                    hn = hreg;
                }
                creg = cn;
                hreg = hn;
                hbuf[(size_t)(t+1)*ROWSZ + eb*HIDD + hbase + ehh] = hn;
            }

            // 9) arrive only; the wait is overlapped with next step's x-GEMM
            grid_arrive();
        }
    }
}

// out[r][a] = h1[r] . Wfc[:,a] + bfc[a],  h1 row = g_hB row r+32
__global__ void __launch_bounds__(256)
fc_kernel(const float* __restrict__ Wfc, const float* __restrict__ bfc,
          float* __restrict__ out)
{
    __shared__ float w_s[128*64];
    __shared__ float h_s[32*128];
    const int tid = threadIdx.x;
    const int rbase = blockIdx.x * 32;
    const int a  = tid & 63;
    const int r4 = tid >> 6;

    float acc[8];
    float bvv = bfc[a];
    #pragma unroll
    for (int j = 0; j < 8; ++j) acc[j] = bvv;

    for (int kc = 0; kc < 512; kc += 128) {
        __syncthreads();
        for (int i = tid; i < 128*64/4; i += 256)
            ((float4*)w_s)[i] = ((const float4*)(Wfc + (size_t)kc*64))[i];
        for (int i = tid; i < 32*128/4; i += 256) {
            int r  = i >> 5;
            int k4 = i & 31;
            ((float4*)(h_s + r*128))[k4] =
                *(const float4*)(g_hB + (size_t)(rbase + r + BB)*HIDD + kc + (k4 << 2));
        }
        __syncthreads();
        #pragma unroll 4
        for (int k = 0; k < 128; ++k) {
            float w = w_s[(k << 6) + a];
            #pragma unroll
            for (int j = 0; j < 8; ++j)
                acc[j] += h_s[(r4 + 4*j)*128 + k] * w;
        }
    }
    #pragma unroll
    for (int j = 0; j < 8; ++j)
        out[(size_t)(rbase + r4 + 4*j)*64 + a] = acc[j];
}

extern "C" void kernel_launch(void* const* d_in, const int* in_sizes, int n_in,
                              void* d_out, int out_size)
{
    const float* x      = (const float*)d_in[0];
    const void*  length = (const void*)d_in[1];
    const float* Wih0   = (const float*)d_in[2];
    const float* Whh0   = (const float*)d_in[3];
    const float* b0v    = (const float*)d_in[4];
    const float* Wih1   = (const float*)d_in[5];
    const float* Whh1   = (const float*)d_in[6];
    const float* b1v    = (const float*)d_in[7];
    const float* Wfc    = (const float*)d_in[8];
    const float* bfc    = (const float*)d_in[9];
    float* out = (float*)d_out;

    const int smem_bytes = SMEM_FLOATS * (int)sizeof(float); // ~194 KB
    cudaFuncSetAttribute(lstm_persistent,
                         cudaFuncAttributeMaxDynamicSharedMemorySize, smem_bytes);

    lstm_persistent<<<NCTA, NTHR, smem_bytes>>>(x, length, Wih0, Whh0, b0v,
                                                Wih1, Whh1, b1v);
    fc_kernel<<<(TT*BB)/32, 256>>>(Wfc, bfc, out);
}

// round 13
// speedup vs baseline: 1.7890x; 1.0040x over previous
#include <cuda_runtime.h>

#define TT    2048
#define BB    32
#define FEATD 512
#define HIDD  512
#define NCOL4 2048
#define NCTA  128
#define NH    4
#define NC    16
#define NTHR  256
#define ROWSZ (BB*HIDD)      // 16384 floats per timestep of h

// smem layout (floats)
#define ZX_OFF   0            // z_x: [32][512]
#define ZH_OFF   16384        // z_h: [32][512]
#define W_OFF    32768        // W_s: 16384
#define G_OFF    49152        // gates: 32*17
#define SMEM_FLOATS (G_OFF + 32*17)   // ~194 KB

__device__ __align__(256) float g_hA[(TT+1)*ROWSZ];
__device__ __align__(256) float g_hB[(TT+1)*ROWSZ];
__device__ unsigned int g_count = 0;
__device__ unsigned int g_gen   = 0;

// JAX silently downcasts int64->int32 unless x64 mode is on; detect at runtime.
__device__ __forceinline__ int load_length(const void* lp, int b) {
    const int* L = (const int*)lp;
    bool is64 = true;
    #pragma unroll
    for (int w = 1; w < 32; w += 2) is64 &= (L[w] == 0);
    return is64 ? (int)((const long long*)lp)[b] : L[b];
}

__device__ __forceinline__ void cpa16(unsigned int dst, const void* src) {
    asm volatile("cp.async.cg.shared.global [%0], [%1], 16;" :: "r"(dst), "l"(src));
}
#define CPA_COMMIT() asm volatile("cp.async.commit_group;")
#define CPA_WAIT0()  asm volatile("cp.async.wait_group 0;")

__device__ __forceinline__ unsigned int smem_u32(const void* p) {
    unsigned int a;
    asm("{ .reg .u64 t; cvta.to.shared.u64 t, %1; cvt.u32.u64 %0, t; }" : "=r"(a) : "l"(p));
    return a;
}

// hardware tanh (sm_75+): 1 MUFU op, max abs err ~1e-4
__device__ __forceinline__ float tanhapx(float x) {
    float y;
    asm("tanh.approx.f32 %0, %1;" : "=f"(y) : "f"(x));
    return y;
}

// Split grid barrier (single-counter, R6-proven atomics).
// arrive: non-blocking; last arriver resets count and bumps gen (monotonic
// across graph replays -> launch state always clean).
__device__ __forceinline__ void grid_arrive() {
    __threadfence();
    __syncthreads();
    if (threadIdx.x == 0) {
        if (atomicAdd(&g_count, 1u) == NCTA - 1u) {
            atomicExch(&g_count, 0u);
            __threadfence();
            atomicAdd(&g_gen, 1u);
        }
    }
}
// wait: block until gen reaches target (wrap-safe compare).
__device__ __forceinline__ void grid_wait(unsigned int target) {
    if (threadIdx.x == 0) {
        volatile unsigned int* vg = &g_gen;
        while ((int)(*vg - target) < 0) {}
    }
    __syncthreads();
}

__global__ void __launch_bounds__(NTHR, 1)
lstm_persistent(const float* __restrict__ x,
                const void* __restrict__ length,
                const float* __restrict__ Wih0, const float* __restrict__ Whh0,
                const float* __restrict__ b0v,
                const float* __restrict__ Wih1, const float* __restrict__ Whh1,
                const float* __restrict__ b1v)
{
    extern __shared__ float smem[];
    float* z_x     = smem + ZX_OFF;
    float* z_h     = smem + ZH_OFF;
    float* W_s     = smem + W_OFF;
    float* gates_s = smem + G_OFF;
    const unsigned int zx_u = smem_u32(z_x);
    const unsigned int zh_u = smem_u32(z_h);

    const int tid   = threadIdx.x;
    const int hbase = blockIdx.x * NH;

    // gen base at launch: stable until every CTA has arrived at barrier 0.
    const unsigned int bar_base = *((volatile unsigned int*)&g_gen);

    const int c   = tid & 15;              // gate column (c = hh*4 + gate)
    const int bh  = (tid >> 4) & 1;
    const int bg  = (tid >> 5) & 3;
    const int kh  = tid >> 7;              // k-half within each 512-K block
    const int b0i = bg*8 + bh*4;           // 4 batch rows per thread

    const int eb  = tid & 31;              // elementwise mapping (tid<128)
    const int ehh = tid >> 5;
    int lb = 0;
    if (tid < 128) lb = load_length(length, eb);

    for (int layer = 0; layer < 2; ++layer) {
        const float* Wih  = layer ? Wih1 : Wih0;
        const float* Whh  = layer ? Whh1 : Whh0;
        const float* bias = layer ? b1v  : b0v;
        const float* xbase = layer ? (g_hA + ROWSZ) : x;
        float* hbuf = layer ? g_hB : g_hA;

        // Stage weights: W_s[(k>>2)*64 + c*4 + (k&3)] = W[k][col(c)]
        __syncthreads();
        for (int i = tid; i < 1024*NC; i += NTHR) {
            int k  = i >> 4;
            int cc = i & 15;
            int col = ((cc & 3) << 9) + hbase + (cc >> 2);
            float w = (k < FEATD) ? Wih[(size_t)k*NCOL4 + col]
                                  : Whh[(size_t)(k-FEATD)*NCOL4 + col];
            W_s[((k >> 2) << 6) + (cc << 2) + (k & 3)] = w;
        }
        float bv = bias[((c & 3) << 9) + hbase + (c >> 2)];

        // load x(0) into z_x  (layer 1: g_hA row 1, visible since this CTA
        // already observed gen >= bar_base+TT-1 during layer 0)
        {
            const float* xrow = xbase;
            #pragma unroll
            for (int j = 0; j < 16; ++j) {
                int i = tid + j*NTHR;
                int b = i >> 7, k4 = i & 127;
                cpa16(zx_u + ((b << 9) + (k4 << 2))*4, xrow + b*512 + (k4 << 2));
            }
            CPA_COMMIT();
        }
        CPA_WAIT0();
        __syncthreads();

        float creg = 0.f, hreg = 0.f;

        for (int t = 0; t < TT; ++t) {
            // 1) prefetch x(t+1) into registers (latency hidden by x-GEMM)
            float4 xp[16];
            {
                int tn = (t + 1 < TT) ? (t + 1) : (TT - 1);
                const float4* xnext = (const float4*)(xbase + (size_t)tn*ROWSZ);
                #pragma unroll
                for (int j = 0; j < 16; ++j)
                    xp[j] = __ldcg(xnext + tid + j*NTHR);
            }

            float a0 = 0.f, a1 = 0.f, a2 = 0.f, a3 = 0.f;

            const float* wpx = W_s + ((kh*256) >> 2)*64 + (c << 2);
            const float* zpx = z_x + b0i*512 + kh*256;

            // 2a) x-GEMM half 1: k4 in [0,32) — absorbs CTA skew
            #pragma unroll 8
            for (int k4 = 0; k4 < 32; ++k4) {
                float4 w  = *(const float4*)(wpx + (k4 << 6));
                float4 z0 = *(const float4*)(zpx + (k4 << 2));
                float4 z1 = *(const float4*)(zpx + 512  + (k4 << 2));
                float4 z2 = *(const float4*)(zpx + 1024 + (k4 << 2));
                float4 z3 = *(const float4*)(zpx + 1536 + (k4 << 2));
                a0 += z0.x*w.x; a0 += z0.y*w.y; a0 += z0.z*w.z; a0 += z0.w*w.w;
                a1 += z1.x*w.x; a1 += z1.y*w.y; a1 += z1.z*w.z; a1 += z1.w*w.w;
                a2 += z2.x*w.x; a2 += z2.y*w.y; a2 += z2.z*w.z; a2 += z2.w*w.w;
                a3 += z3.x*w.x; a3 += z3.y*w.y; a3 += z3.z*w.z; a3 += z3.w*w.w;
            }

            // 3) wait for h(t) visibility (usually already satisfied), then
            //    issue h staging so its transfer hides under x-GEMM half 2
            grid_wait(bar_base + (unsigned)(layer*TT + t));
            {
                const float* hrow = hbuf + (size_t)t*ROWSZ;
                #pragma unroll
                for (int j = 0; j < 16; ++j) {
                    int i = tid + j*NTHR;
                    int b = i >> 7, k4 = i & 127;
                    cpa16(zh_u + ((b << 9) + (k4 << 2))*4, hrow + b*512 + (k4 << 2));
                }
                CPA_COMMIT();
            }

            // 2b) x-GEMM half 2: k4 in [32,64)
            #pragma unroll 8
            for (int k4 = 32; k4 < 64; ++k4) {
                float4 w  = *(const float4*)(wpx + (k4 << 6));
                float4 z0 = *(const float4*)(zpx + (k4 << 2));
                float4 z1 = *(const float4*)(zpx + 512  + (k4 << 2));
                float4 z2 = *(const float4*)(zpx + 1024 + (k4 << 2));
                float4 z3 = *(const float4*)(zpx + 1536 + (k4 << 2));
                a0 += z0.x*w.x; a0 += z0.y*w.y; a0 += z0.z*w.z; a0 += z0.w*w.w;
                a1 += z1.x*w.x; a1 += z1.y*w.y; a1 += z1.z*w.z; a1 += z1.w*w.w;
                a2 += z2.x*w.x; a2 += z2.y*w.y; a2 += z2.z*w.z; a2 += z2.w*w.w;
                a3 += z3.x*w.x; a3 += z3.y*w.y; a3 += z3.z*w.z; a3 += z3.w*w.w;
            }

            // 4) h resident + all z_x reads of step t closed
            CPA_WAIT0();
            __syncthreads();

            // 5) store x(t+1) to z_x (overlaps with h-GEMM issue below)
            #pragma unroll
            for (int j = 0; j < 16; ++j) {
                int i = tid + j*NTHR;
                int b = i >> 7, k4 = i & 127;
                *(float4*)(z_x + (b << 9) + (k4 << 2)) = xp[j];
            }

            // 6) h-GEMM: k in [512,1024)
            {
                const float* wp = W_s + ((512 + kh*256) >> 2)*64 + (c << 2);
                const float* zp = z_h + b0i*512 + kh*256;
                #pragma unroll 8
                for (int k4 = 0; k4 < 64; ++k4) {
                    float4 w  = *(const float4*)(wp + (k4 << 6));
                    float4 z0 = *(const float4*)(zp + (k4 << 2));
                    float4 z1 = *(const float4*)(zp + 512  + (k4 << 2));
                    float4 z2 = *(const float4*)(zp + 1024 + (k4 << 2));
                    float4 z3 = *(const float4*)(zp + 1536 + (k4 << 2));
                    a0 += z0.x*w.x; a0 += z0.y*w.y; a0 += z0.z*w.z; a0 += z0.w*w.w;
                    a1 += z1.x*w.x; a1 += z1.y*w.y; a1 += z1.z*w.z; a1 += z1.w*w.w;
                    a2 += z2.x*w.x; a2 += z2.y*w.y; a2 += z2.z*w.z; a2 += z2.w*w.w;
                    a3 += z3.x*w.x; a3 += z3.y*w.y; a3 += z3.z*w.z; a3 += z3.w*w.w;
                }
            }

            // 7) cross-kh reduce via smem
            if (kh == 1) {
                gates_s[(b0i+0)*17 + c] = a0;
                gates_s[(b0i+1)*17 + c] = a1;
                gates_s[(b0i+2)*17 + c] = a2;
                gates_s[(b0i+3)*17 + c] = a3;
            }
            __syncthreads();
            if (kh == 0) {
                gates_s[(b0i+0)*17 + c] += a0 + bv;
                gates_s[(b0i+1)*17 + c] += a1 + bv;
                gates_s[(b0i+2)*17 + c] += a2 + bv;
                gates_s[(b0i+3)*17 + c] += a3 + bv;
            }
            __syncthreads();

            // 8) LSTM elementwise via hardware tanh (1 MUFU per activation):
            //    sigmoid(x) = 0.5*tanh(x/2) + 0.5
            if (tid < 128) {
                float fg = gates_s[eb*17 + ehh*4 + 0];
                float ig = gates_s[eb*17 + ehh*4 + 1];
                float og = gates_s[eb*17 + ehh*4 + 2];
                float gg = gates_s[eb*17 + ehh*4 + 3];
                float cn, hn;
                if (t < lb) {
                    float sf = 0.5f*tanhapx(0.5f*fg) + 0.5f;
                    float si = 0.5f*tanhapx(0.5f*ig) + 0.5f;
                    float so = 0.5f*tanhapx(0.5f*og) + 0.5f;
                    float tg = tanhapx(gg);
                    cn = sf*creg + si*tg;
                    float tc = tanhapx(cn);
                    hn = so*tc;
                } else {
                    cn = creg;
                    hn = hreg;
                }
                creg = cn;
                hreg = hn;
                hbuf[(size_t)(t+1)*ROWSZ + eb*HIDD + hbase + ehh] = hn;
            }

            // 9) arrive only; the wait is overlapped with next step's x-GEMM
            grid_arrive();
        }
    }
}

// out[r][a] = h1[r] . Wfc[:,a] + bfc[a],  h1 row = g_hB row r+32
__global__ void __launch_bounds__(256)
fc_kernel(const float* __restrict__ Wfc, const float* __restrict__ bfc,
          float* __restrict__ out)
{
    __shared__ float w_s[128*64];
    __shared__ float h_s[32*128];
    const int tid = threadIdx.x;
    const int rbase = blockIdx.x * 32;
    const int a  = tid & 63;
    const int r4 = tid >> 6;

    float acc[8];
    float bvv = bfc[a];
    #pragma unroll
    for (int j = 0; j < 8; ++j) acc[j] = bvv;

    for (int kc = 0; kc < 512; kc += 128) {
        __syncthreads();
        for (int i = tid; i < 128*64/4; i += 256)
            ((float4*)w_s)[i] = ((const float4*)(Wfc + (size_t)kc*64))[i];
        for (int i = tid; i < 32*128/4; i += 256) {
            int r  = i >> 5;
            int k4 = i & 31;
            ((float4*)(h_s + r*128))[k4] =
                *(const float4*)(g_hB + (size_t)(rbase + r + BB)*HIDD + kc + (k4 << 2));
        }
        __syncthreads();
        #pragma unroll 4
        for (int k = 0; k < 128; ++k) {
            float w = w_s[(k << 6) + a];
            #pragma unroll
            for (int j = 0; j < 8; ++j)
                acc[j] += h_s[(r4 + 4*j)*128 + k] * w;
        }
    }
    #pragma unroll
    for (int j = 0; j < 8; ++j)
        out[(size_t)(rbase + r4 + 4*j)*64 + a] = acc[j];
}

extern "C" void kernel_launch(void* const* d_in, const int* in_sizes, int n_in,
                              void* d_out, int out_size)
{
    const float* x      = (const float*)d_in[0];
    const void*  length = (const void*)d_in[1];
    const float* Wih0   = (const float*)d_in[2];
    const float* Whh0   = (const float*)d_in[3];
    const float* b0v    = (const float*)d_in[4];
    const float* Wih1   = (const float*)d_in[5];
    const float* Whh1   = (const float*)d_in[6];
    const float* b1v    = (const float*)d_in[7];
    const float* Wfc    = (const float*)d_in[8];
    const float* bfc    = (const float*)d_in[9];
    float* out = (float*)d_out;

    const int smem_bytes = SMEM_FLOATS * (int)sizeof(float); // ~194 KB
    cudaFuncSetAttribute(lstm_persistent,
                         cudaFuncAttributeMaxDynamicSharedMemorySize, smem_bytes);

    lstm_persistent<<<NCTA, NTHR, smem_bytes>>>(x, length, Wih0, Whh0, b0v,
                                                Wih1, Whh1, b1v);
    fc_kernel<<<(TT*BB)/32, 256>>>(Wfc, bfc, out);
}